// round 3
// baseline (speedup 1.0000x reference)
#include <cuda_runtime.h>
#include <math.h>

#define HH 512
#define WW 512
#define MM 512
#define NPIX (HH * WW)
#define EPSF 1e-6f
// max_dist = sqrt(512^2 + 512^2)
#define MAXD 724.0773439350246f
// EPS / max_dist
#define CREG 1.3810680e-9f

#define A_BLOCKS 1024   // term1: 1024 blocks * 64 threads, each thread = 4-pixel strip

// Scratch (device globals: no allocation allowed)
static __device__ __align__(16) float g_invp2[NPIX];   // 1/(p^4 + EPS/maxd)^2 per pixel
static __device__ int    g_qmin[MM];                   // column min of d2*invp2, float bits
static __device__ double g_bp[A_BLOCKS];               // per-block sum of p
static __device__ double g_bpd[A_BLOCKS];              // per-block sum of p * min_d

// ---------------------------------------------------------------------------
// Kernel P: precompute invp2, init accumulators/minima
// ---------------------------------------------------------------------------
__global__ void prep_kernel(const float* __restrict__ prob) {
    int i = blockIdx.x * blockDim.x + threadIdx.x;
    if (i < NPIX) {
        float p  = prob[i];
        float p2 = p * p;
        float p4 = p2 * p2;
        float r  = 1.0f / (p4 + CREG);
        g_invp2[i] = r * r;
    }
    if (i < MM) g_qmin[i] = 0x7F800000;  // +inf bits
}

// ---------------------------------------------------------------------------
// Kernel A (term 1): per-pixel min_j d^2. Thread owns 4 vertically adjacent
// pixels at fixed x so dx^2 is computed once per gt point.
// ---------------------------------------------------------------------------
__global__ void __launch_bounds__(64) term1_kernel(const float* __restrict__ prob,
                                                   const float* __restrict__ gt) {
    __shared__ float2 sgt[MM];
    __shared__ double sh_p[64];
    __shared__ double sh_pd[64];

    int tid = threadIdx.x;
    const float2* gt2 = (const float2*)gt;
    for (int i = tid; i < MM; i += 64) sgt[i] = gt2[i];
    __syncthreads();

    int g  = blockIdx.x * 64 + tid;     // 0..65535
    int x  = g & (WW - 1);
    int y0 = (g >> 9) << 2;             // 4-row strip
    float xf  = (float)x;
    float y0f = (float)y0;

    float m0 = 1e30f, m1 = 1e30f, m2 = 1e30f, m3 = 1e30f;

#pragma unroll 4
    for (int j = 0; j < MM; ++j) {
        float2 G  = sgt[j];             // (gy, gx)
        float dx  = xf - G.y;
        float dx2 = dx * dx;
        float u   = y0f - G.x;
        float v1 = u + 1.0f, v2 = u + 2.0f, v3 = u + 3.0f;
        m0 = fminf(m0, fmaf(u,  u,  dx2));
        m1 = fminf(m1, fmaf(v1, v1, dx2));
        m2 = fminf(m2, fmaf(v2, v2, dx2));
        m3 = fminf(m3, fmaf(v3, v3, dx2));
    }

    const float* prow = prob + y0 * WW + x;
    float p0 = prow[0], p1 = prow[WW], p2 = prow[2 * WW], p3 = prow[3 * WW];
    float sp  = (p0 + p1) + (p2 + p3);
    float spd = p0 * sqrtf(m0) + p1 * sqrtf(m1) + p2 * sqrtf(m2) + p3 * sqrtf(m3);

    sh_p[tid]  = (double)sp;
    sh_pd[tid] = (double)spd;
    __syncthreads();
    for (int s = 32; s > 0; s >>= 1) {
        if (tid < s) {
            sh_p[tid]  += sh_p[tid + s];
            sh_pd[tid] += sh_pd[tid + s];
        }
        __syncthreads();
    }
    if (tid == 0) {
        g_bp[blockIdx.x]  = sh_p[0];
        g_bpd[blockIdx.x] = sh_pd[0];
    }
}

// ---------------------------------------------------------------------------
// Kernel B (term 2): one gt point per blockIdx.x, y-range split in blockIdx.y.
// Thread owns 4 adjacent columns (float4 invp2 load); dy^2 shared across them.
// Tracks min_i d2 * invp2; sqrt + EPS-drop applied in the final kernel.
// ---------------------------------------------------------------------------
__global__ void __launch_bounds__(128) term2_kernel(const float* __restrict__ gt) {
    int j = blockIdx.x;
    int t = threadIdx.x;                 // 0..127
    float gy = gt[2 * j];
    float gx = gt[2 * j + 1];

    float c0  = (float)(4 * t);
    float dx0 = c0 - gx,        dx1 = c0 + 1.0f - gx;
    float dx2_ = c0 + 2.0f - gx, dx3 = c0 + 3.0f - gx;
    float e0 = dx0 * dx0, e1 = dx1 * dx1, e2 = dx2_ * dx2_, e3 = dx3 * dx3;

    const float4* P = (const float4*)g_invp2;   // [y*128 + t]
    int ybeg = blockIdx.y * (HH / 4);           // 128 rows per block.y

    float q0 = 1e30f, q1 = 1e30f, q2 = 1e30f, q3 = 1e30f;
    float yi = (float)ybeg;                     // exact integer counter

#pragma unroll 4
    for (int y = ybeg; y < ybeg + HH / 4; ++y) {
        float4 a  = P[y * (WW / 4) + t];
        float dy  = yi - gy;
        yi += 1.0f;
        float dy2 = dy * dy;
        q0 = fminf(q0, (dy2 + e0) * a.x);
        q1 = fminf(q1, (dy2 + e1) * a.y);
        q2 = fminf(q2, (dy2 + e2) * a.z);
        q3 = fminf(q3, (dy2 + e3) * a.w);
    }

    float q = fminf(fminf(q0, q1), fminf(q2, q3));
#pragma unroll
    for (int o = 16; o > 0; o >>= 1)
        q = fminf(q, __shfl_xor_sync(0xFFFFFFFFu, q, o));

    __shared__ float wq[4];
    if ((t & 31) == 0) wq[t >> 5] = q;
    __syncthreads();
    if (t == 0) {
        q = fminf(fminf(wq[0], wq[1]), fminf(wq[2], wq[3]));
        atomicMin(&g_qmin[j], __float_as_int(q));   // positive floats: int order == float order
    }
}

// ---------------------------------------------------------------------------
// Kernel C: deterministic final combine.
// ---------------------------------------------------------------------------
__global__ void __launch_bounds__(512) final_kernel(float* __restrict__ out) {
    __shared__ double shp[512];
    __shared__ double shpd[512];
    __shared__ double shs[512];
    int t = threadIdx.x;

    float q   = __int_as_float(g_qmin[t]);
    float val = fminf(sqrtf(q), MAXD);

    shp[t]  = g_bp[t] + g_bp[t + 512];
    shpd[t] = g_bpd[t] + g_bpd[t + 512];
    shs[t]  = (double)val;
    __syncthreads();
    for (int s = 256; s > 0; s >>= 1) {
        if (t < s) {
            shp[t]  += shp[t + s];
            shpd[t] += shpd[t + s];
            shs[t]  += shs[t + s];
        }
        __syncthreads();
    }
    if (t == 0) {
        double term1 = shpd[0] / (shp[0] + (double)EPSF);
        double term2 = shs[0] / (double)MM;
        out[0] = (float)(term1 + term2);
    }
}

// ---------------------------------------------------------------------------
extern "C" void kernel_launch(void* const* d_in, const int* in_sizes, int n_in,
                              void* d_out, int out_size) {
    // Identify inputs by element count (robust to ordering):
    // prob_map: 262144, gt: 1024, all_img_locations: 524288 (unused; implicit grid)
    const float* prob = nullptr;
    const float* gt   = nullptr;
    for (int i = 0; i < n_in; ++i) {
        if (in_sizes[i] == NPIX)   prob = (const float*)d_in[i];
        else if (in_sizes[i] == 2 * MM) gt = (const float*)d_in[i];
    }
    float* out = (float*)d_out;

    prep_kernel<<<NPIX / 256, 256>>>(prob);
    term1_kernel<<<A_BLOCKS, 64>>>(prob, gt);
    term2_kernel<<<dim3(MM, 4, 1), 128>>>(gt);
    final_kernel<<<1, 512>>>(out);
}

// round 8
// speedup vs baseline: 2.2018x; 2.2018x over previous
#include <cuda_runtime.h>
#include <math.h>

#define HH 512
#define WW 512
#define MM 512
#define EPSF 1e-6f
// max_dist = sqrt(512^2 + 512^2)
#define MAXD 724.0773439350246f
// EPS / max_dist
#define CREG 1.3810680e-9f

#define T1_BLOCKS 1024              // 32x32 tiles of 16x16 pixels
#define T2_BLOCKS 64                // 64 blocks * 8 warps = 512 gt points
#define GRID_TOT (T1_BLOCKS + T2_BLOCKS)
#define TWO_HD   22.62741699796952f // 2 * 8*sqrt(2): tile half-diagonal * 2

// Device-global scratch (no allocation allowed)
static __device__ double g_bp[T1_BLOCKS];   // per-tile sum of p
static __device__ double g_bpd[T1_BLOCKS];  // per-tile sum of p * min_dist
static __device__ float  g_q[MM];           // per-gt clamped column min
static __device__ unsigned int g_done;      // zero at module load; last block resets

__global__ void __launch_bounds__(256) chamfer_kernel(
    const float* __restrict__ prob,
    const float* __restrict__ gt,
    float* __restrict__ out)
{
    __shared__ float2 scand[MM];     // candidate gt coords for this tile
    __shared__ int    scnt;
    __shared__ double sA[256];
    __shared__ double sB[256];
    __shared__ double sC[256];
    __shared__ float  swm[8];
    __shared__ int    s_last;

    const int b   = blockIdx.x;
    const int tid = threadIdx.x;

    if (b < T1_BLOCKS) {
        // ================= TERM 1: one 16x16 pixel tile per block =========
        const int ty = b >> 5, tx = b & 31;
        const float cy = (float)(ty * 16) + 7.5f;
        const float cx = (float)(tx * 16) + 7.5f;
        const float2* gt2 = (const float2*)gt;

        // pass 1: min squared distance from tile center to any gt
        float md = 1e30f;
        for (int j = tid; j < MM; j += 256) {
            float2 G = gt2[j];                 // (y, x)
            float dy = cy - G.x, dx = cx - G.y;
            md = fminf(md, fmaf(dy, dy, dx * dx));
        }
        for (int o = 16; o > 0; o >>= 1)
            md = fminf(md, __shfl_xor_sync(0xFFFFFFFFu, md, o));
        if ((tid & 31) == 0) swm[tid >> 5] = md;
        if (tid == 0) scnt = 0;
        __syncthreads();
        float mdall = fminf(fminf(fminf(swm[0], swm[1]), fminf(swm[2], swm[3])),
                            fminf(fminf(swm[4], swm[5]), fminf(swm[6], swm[7])));
        // any gt that can be nearest for some pixel in tile lies within
        // sqrt(mdall) + 2*half_diag of the center (exact; +0.01 fp slack)
        float T  = sqrtf(mdall) + TWO_HD + 1e-2f;
        float T2 = T * T;

        // pass 2: compact candidates into smem (order irrelevant for min)
        for (int j = tid; j < MM; j += 256) {
            float2 G = gt2[j];
            float dy = cy - G.x, dx = cx - G.y;
            if (fmaf(dy, dy, dx * dx) <= T2) {
                int k = atomicAdd(&scnt, 1);
                scand[k] = G;
            }
        }
        __syncthreads();
        const int cnt = scnt;

        // per-pixel nearest over candidates
        const int py = (ty << 4) + (tid >> 4);
        const int px = (tx << 4) + (tid & 15);
        const float fy = (float)py, fx = (float)px;
        float m = 1e30f;
        for (int k = 0; k < cnt; ++k) {
            float2 G = scand[k];
            float dy = fy - G.x, dx = fx - G.y;
            m = fminf(m, fmaf(dy, dy, dx * dx));
        }
        float p = prob[py * WW + px];
        sA[tid] = (double)p;
        sB[tid] = (double)(p * sqrtf(m));
        __syncthreads();
        for (int s = 128; s > 0; s >>= 1) {
            if (tid < s) { sA[tid] += sA[tid + s]; sB[tid] += sB[tid + s]; }
            __syncthreads();
        }
        if (tid == 0) { g_bp[b] = sA[0]; g_bpd[b] = sB[0]; }
    } else {
        // ================= TERM 2: one gt point per warp ==================
        const int lane = tid & 31;
        const int w = (b - T1_BLOCKS) * 8 + (tid >> 5);   // 0..511
        const float gy = gt[2 * w];
        const float gx = gt[2 * w + 1];
        const int iy = (int)gy;   // floor (coords >= 0)
        const int ix = (int)gx;

        // expanding-box exact search: pixels outside box radius R have d > R,
        // and value >= d*(1 - 1.4e-9), so stop once R >= min(q_best, MAXD).
        float qb = 1e30f;
        int R = 4;
        for (;;) {
            int y0 = max(iy - R, 0), y1 = min(iy + R, HH - 1);
            int x0 = max(ix - R, 0), x1 = min(ix + R, WW - 1);
            float q = 1e30f;
            for (int yy = y0; yy <= y1; ++yy) {
                float dy  = (float)yy - gy;
                float dy2 = dy * dy;
                const float* prow = prob + yy * WW;
                for (int xx = x0 + lane; xx <= x1; xx += 32) {
                    float p  = prow[xx];
                    float dx = (float)xx - gx;
                    float d  = sqrtf(fmaf(dx, dx, dy2));
                    float p2 = p * p;
                    float v  = __fdividef(d + EPSF, fmaf(p2, p2, CREG));
                    q = fminf(q, v);
                }
            }
            for (int o = 16; o > 0; o >>= 1)
                q = fminf(q, __shfl_xor_sync(0xFFFFFFFFu, q, o));
            qb = q;   // box rescans include all previously scanned pixels
            float bound = fminf(qb, MAXD);
            if ((float)R >= bound) break;
            if (y0 == 0 && x0 == 0 && y1 == HH - 1 && x1 == WW - 1) break;
            int Rn = (int)bound + 1;
            R = max(Rn, R * 2);   // guaranteed progress; terminates at full image
        }
        if (lane == 0) g_q[w] = fminf(qb, MAXD);
    }

    // ============ completion detection + final reduce by last block =======
    __threadfence();
    __syncthreads();
    if (tid == 0) {
        unsigned int prev = atomicAdd(&g_done, 1u);
        s_last = (prev == GRID_TOT - 1) ? 1 : 0;
    }
    __syncthreads();
    if (s_last) {
        double bp = 0.0, bpd = 0.0;
#pragma unroll
        for (int i = 0; i < 4; ++i) {
            bp  += g_bp[tid + 256 * i];
            bpd += g_bpd[tid + 256 * i];
        }
        double qs = (double)g_q[tid] + (double)g_q[tid + 256];
        sA[tid] = bp; sB[tid] = bpd; sC[tid] = qs;
        __syncthreads();
        for (int s = 128; s > 0; s >>= 1) {
            if (tid < s) {
                sA[tid] += sA[tid + s];
                sB[tid] += sB[tid + s];
                sC[tid] += sC[tid + s];
            }
            __syncthreads();
        }
        if (tid == 0) {
            double term1 = sB[0] / (sA[0] + (double)EPSF);
            double term2 = sC[0] / (double)MM;
            out[0] = (float)(term1 + term2);
            g_done = 0;              // reset for next graph replay
            __threadfence();
        }
    }
}

extern "C" void kernel_launch(void* const* d_in, const int* in_sizes, int n_in,
                              void* d_out, int out_size) {
    // prob_map: 262144 elems, gt: 1024 elems, all_img_locations: 524288 (implicit)
    const float* prob = nullptr;
    const float* gt   = nullptr;
    for (int i = 0; i < n_in; ++i) {
        if (in_sizes[i] == HH * WW)      prob = (const float*)d_in[i];
        else if (in_sizes[i] == 2 * MM)  gt   = (const float*)d_in[i];
    }
    chamfer_kernel<<<GRID_TOT, 256>>>(prob, gt, (float*)d_out);
}

// round 10
// speedup vs baseline: 2.8314x; 1.2860x over previous
#include <cuda_runtime.h>
#include <math.h>

#define HH 512
#define WW 512
#define MM 512
#define EPSF 1e-6f
// max_dist = sqrt(512^2 + 512^2)
#define MAXD 724.0773439350246f
// EPS / max_dist
#define CREG 1.3810680e-9f

#define T2_BLOCKS 64                // blocks 0..63: term2, 8 warps = 8 gt pts each
#define T1_BLOCKS 1024              // blocks 64..1087: term1, 16x16 pixel tiles
#define GRID_TOT (T1_BLOCKS + T2_BLOCKS)
#define TWO_HD   22.62741699796952f // 2 * 8*sqrt(2): tile half-diagonal * 2

// Device-global scratch (no allocation allowed)
static __device__ float g_bp[T1_BLOCKS];    // per-tile sum of p
static __device__ float g_bpd[T1_BLOCKS];   // per-tile sum of p * min_dist
static __device__ float g_q[MM];            // per-gt clamped column min
static __device__ unsigned int g_done;      // zero at load; last block resets

__device__ __forceinline__ float warp_min(float v) {
#pragma unroll
    for (int o = 16; o > 0; o >>= 1)
        v = fminf(v, __shfl_xor_sync(0xFFFFFFFFu, v, o));
    return v;
}
__device__ __forceinline__ float warp_sum(float v) {
#pragma unroll
    for (int o = 16; o > 0; o >>= 1)
        v += __shfl_xor_sync(0xFFFFFFFFu, v, o);
    return v;
}

__global__ void __launch_bounds__(256) chamfer_kernel(
    const float* __restrict__ prob,
    const float* __restrict__ gt,
    float* __restrict__ out)
{
    __shared__ float2 scand[MM];     // candidate gt coords for this tile
    __shared__ int    scnt;
    __shared__ float  sA[256];
    __shared__ float  sB[256];
    __shared__ float  sC[256];
    __shared__ float  swm[8];
    __shared__ int    s_last;

    const int b    = blockIdx.x;
    const int tid  = threadIdx.x;
    const int lane = tid & 31;
    const int wid  = tid >> 5;

    if (b >= T2_BLOCKS) {
        // ================= TERM 1: one 16x16 pixel tile per block =========
        const int tb = b - T2_BLOCKS;
        const int ty = tb >> 5, tx = tb & 31;
        const float cy = (float)(ty * 16) + 7.5f;
        const float cx = (float)(tx * 16) + 7.5f;
        const float2* gt2 = (const float2*)gt;

        // pass 1: min squared distance from tile center to any gt
        float md = 1e30f;
        {
            float2 Ga = gt2[tid];
            float2 Gb = gt2[tid + 256];
            float dya = cy - Ga.x, dxa = cx - Ga.y;
            float dyb = cy - Gb.x, dxb = cx - Gb.y;
            md = fminf(fmaf(dya, dya, dxa * dxa), fmaf(dyb, dyb, dxb * dxb));
        }
        md = warp_min(md);
        if (lane == 0) swm[wid] = md;
        if (tid == 0) scnt = 0;
        __syncthreads();
        float mdall = fminf(fminf(fminf(swm[0], swm[1]), fminf(swm[2], swm[3])),
                            fminf(fminf(swm[4], swm[5]), fminf(swm[6], swm[7])));
        // any gt that can be nearest for some pixel in this tile lies within
        // sqrt(mdall) + 2*half_diag of the center (triangle ineq; +0.01 slack)
        float T  = sqrtf(mdall) + TWO_HD + 1e-2f;
        float T2 = T * T;

        // pass 2: compact candidates into smem (order irrelevant for min)
#pragma unroll
        for (int r = 0; r < 2; ++r) {
            int j = tid + r * 256;
            float2 G = gt2[j];
            float dy = cy - G.x, dx = cx - G.y;
            if (fmaf(dy, dy, dx * dx) <= T2) {
                int k = atomicAdd(&scnt, 1);
                scand[k] = G;
            }
        }
        __syncthreads();
        const int cnt = scnt;

        // per-pixel nearest over candidates (2 independent min chains)
        const int py = (ty << 4) + (tid >> 4);
        const int px = (tx << 4) + (tid & 15);
        const float fy = (float)py, fx = (float)px;
        float ma = 1e30f, mb = 1e30f;
        int k = 0;
        for (; k + 1 < cnt; k += 2) {
            float2 G0 = scand[k];
            float2 G1 = scand[k + 1];
            float dy0 = fy - G0.x, dx0 = fx - G0.y;
            float dy1 = fy - G1.x, dx1 = fx - G1.y;
            ma = fminf(ma, fmaf(dy0, dy0, dx0 * dx0));
            mb = fminf(mb, fmaf(dy1, dy1, dx1 * dx1));
        }
        if (k < cnt) {
            float2 G = scand[k];
            float dy = fy - G.x, dx = fx - G.y;
            ma = fminf(ma, fmaf(dy, dy, dx * dx));
        }
        float m = fminf(ma, mb);

        float p  = prob[py * WW + px];
        float sp  = warp_sum(p);
        float spd = warp_sum(p * sqrtf(m));
        if (lane == 0) { sA[wid] = sp; sB[wid] = spd; }
        __syncthreads();
        if (tid == 0) {
            float a = ((sA[0] + sA[1]) + (sA[2] + sA[3]))
                    + ((sA[4] + sA[5]) + (sA[6] + sA[7]));
            float d = ((sB[0] + sB[1]) + (sB[2] + sB[3]))
                    + ((sB[4] + sB[5]) + (sB[6] + sB[7]));
            g_bp[tb]  = a;
            g_bpd[tb] = d;
        }
    } else {
        // ================= TERM 2: one gt point per warp ==================
        const int w = b * 8 + wid;              // 0..511
        const float gy = gt[2 * w];
        const float gx = gt[2 * w + 1];
        const int iy = (int)gy;                 // floor (coords >= 0)
        const int ix = (int)gx;

        // expanding-box exact search: pixels outside box radius R have d > R,
        // and value >= d*(1 - 1.4e-9), so stop once R >= min(q_best, MAXD).
        float qb = 1e30f;
        int R = 4;
        for (;;) {
            int y0 = max(iy - R, 0), y1 = min(iy + R, HH - 1);
            int x0 = max(ix - R, 0), x1 = min(ix + R, WW - 1);
            float q = 1e30f;
            for (int yy = y0; yy <= y1; ++yy) {
                float dy  = (float)yy - gy;
                float dy2 = dy * dy;
                const float* prow = prob + yy * WW;
                for (int xx = x0 + lane; xx <= x1; xx += 32) {
                    float p  = prow[xx];
                    float dx = (float)xx - gx;
                    float d  = sqrtf(fmaf(dx, dx, dy2));
                    float p2 = p * p;
                    float v  = __fdividef(d + EPSF, fmaf(p2, p2, CREG));
                    q = fminf(q, v);
                }
            }
            q  = warp_min(q);
            qb = q;   // box rescans include all previously scanned pixels
            float bound = fminf(qb, MAXD);
            if ((float)R >= bound) break;
            if (y0 == 0 && x0 == 0 && y1 == HH - 1 && x1 == WW - 1) break;
            int Rn = (int)bound + 1;
            R = max(Rn, R * 2);   // guaranteed progress; terminates at image
        }
        if (lane == 0) g_q[w] = fminf(qb, MAXD);
    }

    // ============ completion detection + final reduce by last block =======
    __threadfence();
    __syncthreads();
    if (tid == 0) {
        unsigned int prev = atomicAdd(&g_done, 1u);
        s_last = (prev == GRID_TOT - 1) ? 1 : 0;
    }
    __syncthreads();
    if (s_last) {
        // pairwise f32 combine: 1024 tile partials, 512 gt minima
        float bp  = (g_bp[tid]        + g_bp[tid + 256])
                  + (g_bp[tid + 512]  + g_bp[tid + 768]);
        float bpd = (g_bpd[tid]       + g_bpd[tid + 256])
                  + (g_bpd[tid + 512] + g_bpd[tid + 768]);
        float qs  = g_q[tid] + g_q[tid + 256];
        sA[tid] = bp; sB[tid] = bpd; sC[tid] = qs;
        __syncthreads();
        for (int s = 128; s > 0; s >>= 1) {
            if (tid < s) {
                sA[tid] += sA[tid + s];
                sB[tid] += sB[tid + s];
                sC[tid] += sC[tid + s];
            }
            __syncthreads();
        }
        if (tid == 0) {
            float term1 = sB[0] / (sA[0] + EPSF);
            float term2 = sC[0] * (1.0f / (float)MM);
            out[0] = term1 + term2;
            g_done = 0;              // reset for next graph replay
            __threadfence();
        }
    }
}

extern "C" void kernel_launch(void* const* d_in, const int* in_sizes, int n_in,
                              void* d_out, int out_size) {
    // prob_map: 262144 elems, gt: 1024 elems, all_img_locations: implicit
    const float* prob = nullptr;
    const float* gt   = nullptr;
    for (int i = 0; i < n_in; ++i) {
        if (in_sizes[i] == HH * WW)      prob = (const float*)d_in[i];
        else if (in_sizes[i] == 2 * MM)  gt   = (const float*)d_in[i];
    }
    chamfer_kernel<<<GRID_TOT, 256>>>(prob, gt, (float*)d_out);
}

// round 13
// speedup vs baseline: 3.8333x; 1.3538x over previous
#include <cuda_runtime.h>
#include <math.h>

#define HH 512
#define WW 512
#define MM 512
#define EPSF 1e-6f
// max_dist = sqrt(512^2 + 512^2)
#define MAXD 724.0773439350246f
// EPS / max_dist
#define CREG 1.3810680e-9f

#define T2_BLOCKS 64                // blocks 0..63: term2, 8 warps = 8 gt pts each
#define T1_BLOCKS 256               // blocks 64..319: term1, 32x32 pixel tiles
#define GRID_TOT (T1_BLOCKS + T2_BLOCKS)
#define TWO_HD   45.254833995939045f // 2 * 16*sqrt(2): tile half-diagonal * 2

// Device-global scratch (no allocation allowed)
static __device__ float g_bp[T1_BLOCKS];    // per-tile sum of p
static __device__ float g_bpd[T1_BLOCKS];   // per-tile sum of p * min_dist
static __device__ float g_q[MM];            // per-gt clamped column min
static __device__ unsigned int g_done;      // zero at load; last block resets

__device__ __forceinline__ float warp_min(float v) {
#pragma unroll
    for (int o = 16; o > 0; o >>= 1)
        v = fminf(v, __shfl_xor_sync(0xFFFFFFFFu, v, o));
    return v;
}
__device__ __forceinline__ float warp_sum(float v) {
#pragma unroll
    for (int o = 16; o > 0; o >>= 1)
        v += __shfl_xor_sync(0xFFFFFFFFu, v, o);
    return v;
}

__global__ void __launch_bounds__(256) chamfer_kernel(
    const float* __restrict__ prob,
    const float* __restrict__ gt,
    float* __restrict__ out)
{
    __shared__ float2 scand[MM];     // candidate gt coords for this tile
    __shared__ int    scnt;
    __shared__ float  sA[256];
    __shared__ float  sB[256];
    __shared__ float  sC[256];
    __shared__ float  swm[8];
    __shared__ int    s_last;

    const int b    = blockIdx.x;
    const int tid  = threadIdx.x;
    const int lane = tid & 31;
    const int wid  = tid >> 5;

    if (b >= T2_BLOCKS) {
        // ============ TERM 1: one 32x32 pixel tile per block ==============
        // thread owns a 4-row strip: x = tx*32 + (tid&31), y = ty*32+(tid>>5)*4 ..+3
        const int tb = b - T2_BLOCKS;
        const int ty = tb >> 3, tx = tb & 7;          // 16x8? no: 512/32=16 tiles/side
        // 16 x 16 tile grid: tb in [0,256): ty = tb>>4, tx = tb&15
        const int tyy = tb >> 4, txx = tb & 15;
        const float cy = (float)(tyy * 32) + 15.5f;
        const float cx = (float)(txx * 32) + 15.5f;
        (void)ty; (void)tx;
        const float2* gt2 = (const float2*)gt;

        // pass 1: per-thread distances to 2 gt points (kept for pass 2)
        float2 Ga = gt2[tid];
        float2 Gb = gt2[tid + 256];
        float dya = cy - Ga.x, dxa = cx - Ga.y;
        float dyb = cy - Gb.x, dxb = cx - Gb.y;
        float d2a = fmaf(dya, dya, dxa * dxa);
        float d2b = fmaf(dyb, dyb, dxb * dxb);

        float md = warp_min(fminf(d2a, d2b));
        if (lane == 0) swm[wid] = md;
        if (tid == 0) scnt = 0;
        __syncthreads();
        float mdall = fminf(fminf(fminf(swm[0], swm[1]), fminf(swm[2], swm[3])),
                            fminf(fminf(swm[4], swm[5]), fminf(swm[6], swm[7])));
        // a gt can be nearest for some pixel of this tile only if its distance
        // to the center is <= sqrt(mdall) + 2*half_diag  (triangle ineq + slack)
        float T  = sqrtf(mdall) + TWO_HD + 1e-2f;
        float T2 = T * T;

        // pass 2: compact candidates (reuse registers, no gt reload)
        if (d2a <= T2) { int k = atomicAdd(&scnt, 1); scand[k] = Ga; }
        if (d2b <= T2) { int k = atomicAdd(&scnt, 1); scand[k] = Gb; }
        __syncthreads();
        const int cnt = scnt;

        // per-pixel nearest: 4 vertically adjacent pixels, dx^2 hoisted
        const int px = (txx << 5) + lane;
        const int py0 = (tyy << 5) + (wid << 2);
        const float fx  = (float)px;
        const float fy0 = (float)py0;
        float m0 = 1e30f, m1 = 1e30f, m2 = 1e30f, m3 = 1e30f;
        for (int k = 0; k < cnt; ++k) {
            float2 G   = scand[k];
            float dx   = fx - G.y;
            float dx2  = dx * dx;
            float u    = fy0 - G.x;
            float v1 = u + 1.0f, v2 = u + 2.0f, v3 = u + 3.0f;
            m0 = fminf(m0, fmaf(u,  u,  dx2));
            m1 = fminf(m1, fmaf(v1, v1, dx2));
            m2 = fminf(m2, fmaf(v2, v2, dx2));
            m3 = fminf(m3, fmaf(v3, v3, dx2));
        }

        const float* prow = prob + py0 * WW + px;
        float p0 = prow[0], p1 = prow[WW], p2 = prow[2 * WW], p3 = prow[3 * WW];
        float sp  = (p0 + p1) + (p2 + p3);
        float spd = (p0 * sqrtf(m0) + p1 * sqrtf(m1))
                  + (p2 * sqrtf(m2) + p3 * sqrtf(m3));
        sp  = warp_sum(sp);
        spd = warp_sum(spd);
        if (lane == 0) { sA[wid] = sp; sB[wid] = spd; }
        __syncthreads();
        if (tid == 0) {
            float a = ((sA[0] + sA[1]) + (sA[2] + sA[3]))
                    + ((sA[4] + sA[5]) + (sA[6] + sA[7]));
            float d = ((sB[0] + sB[1]) + (sB[2] + sB[3]))
                    + ((sB[4] + sB[5]) + (sB[6] + sB[7]));
            g_bp[tb]  = a;
            g_bpd[tb] = d;
        }
    } else {
        // ================= TERM 2: one gt point per warp ==================
        const int w = b * 8 + wid;              // 0..511
        const float gy = gt[2 * w];
        const float gx = gt[2 * w + 1];
        const int iy = (int)gy;                 // floor (coords >= 0)
        const int ix = (int)gx;

        // expanding-box exact search: pixels outside box radius R have d > R,
        // and value >= d*(1 - 1.4e-9), so stop once R >= min(q_best, MAXD).
        float qb = 1e30f;
        int R = 4;
        for (;;) {
            int y0 = max(iy - R, 0), y1 = min(iy + R, HH - 1);
            int x0 = max(ix - R, 0), x1 = min(ix + R, WW - 1);
            float q = 1e30f;
            for (int yy = y0; yy <= y1; ++yy) {
                float dy  = (float)yy - gy;
                float dy2 = dy * dy;
                const float* prow = prob + yy * WW;
                for (int xx = x0 + lane; xx <= x1; xx += 32) {
                    float p  = prow[xx];
                    float dx = (float)xx - gx;
                    float d  = sqrtf(fmaf(dx, dx, dy2));
                    float p2 = p * p;
                    float v  = __fdividef(d + EPSF, fmaf(p2, p2, CREG));
                    q = fminf(q, v);
                }
            }
            q  = warp_min(q);
            qb = q;   // box rescans include all previously scanned pixels
            float bound = fminf(qb, MAXD);
            if ((float)R >= bound) break;
            if (y0 == 0 && x0 == 0 && y1 == HH - 1 && x1 == WW - 1) break;
            int Rn = (int)bound + 1;
            R = max(Rn, R * 2);   // guaranteed progress; terminates at image
        }
        if (lane == 0) g_q[w] = fminf(qb, MAXD);
    }

    // ============ completion detection + final reduce by last block =======
    __threadfence();
    __syncthreads();
    if (tid == 0) {
        unsigned int prev = atomicAdd(&g_done, 1u);
        s_last = (prev == GRID_TOT - 1) ? 1 : 0;
    }
    __syncthreads();
    if (s_last) {
        // pairwise f32 combine: 256 tile partials, 512 gt minima
        float bp  = g_bp[tid];
        float bpd = g_bpd[tid];
        float qs  = g_q[tid] + g_q[tid + 256];
        sA[tid] = bp; sB[tid] = bpd; sC[tid] = qs;
        __syncthreads();
        for (int s = 128; s > 0; s >>= 1) {
            if (tid < s) {
                sA[tid] += sA[tid + s];
                sB[tid] += sB[tid + s];
                sC[tid] += sC[tid + s];
            }
            __syncthreads();
        }
        if (tid == 0) {
            float term1 = sB[0] / (sA[0] + EPSF);
            float term2 = sC[0] * (1.0f / (float)MM);
            out[0] = term1 + term2;
            g_done = 0;              // reset for next graph replay
            __threadfence();
        }
    }
}

extern "C" void kernel_launch(void* const* d_in, const int* in_sizes, int n_in,
                              void* d_out, int out_size) {
    // prob_map: 262144 elems, gt: 1024 elems, all_img_locations: implicit
    const float* prob = nullptr;
    const float* gt   = nullptr;
    for (int i = 0; i < n_in; ++i) {
        if (in_sizes[i] == HH * WW)      prob = (const float*)d_in[i];
        else if (in_sizes[i] == 2 * MM)  gt   = (const float*)d_in[i];
    }
    chamfer_kernel<<<GRID_TOT, 256>>>(prob, gt, (float*)d_out);
}

// round 16
// speedup vs baseline: 5.3777x; 1.4029x over previous
#include <cuda_runtime.h>
#include <math.h>

#define HH 512
#define WW 512
#define MM 512
#define EPSF 1e-6f
// max_dist = sqrt(512^2 + 512^2)
#define MAXD 724.0773439350246f
// EPS / max_dist
#define CREG 1.3810680e-9f

#define T2_BLOCKS 64                 // blocks 0..63: term2, 8 warps = 8 gt pts each
#define T1_BLOCKS 256                // blocks 64..319: term1, 32x32 pixel tiles
#define GRID_TOT (T1_BLOCKS + T2_BLOCKS)
#define TWO_HD   45.254833995939045f // 2 * 16*sqrt(2): tile half-diagonal * 2

// Device-global scratch (no allocation allowed)
static __device__ __align__(16) float g_bp[T1_BLOCKS];   // per-tile sum of p
static __device__ __align__(16) float g_bpd[T1_BLOCKS];  // per-tile sum p*min_d
static __device__ __align__(16) float g_q[MM];           // per-gt clamped col min
static __device__ unsigned int g_done;                   // zero at load; reset by last block

// single-instruction warp min for NON-NEGATIVE floats (bit order == fp order)
__device__ __forceinline__ float warp_min_pos(float v) {
    return __uint_as_float(__reduce_min_sync(0xFFFFFFFFu, __float_as_uint(v)));
}
__device__ __forceinline__ float warp_sum(float v) {
#pragma unroll
    for (int o = 16; o > 0; o >>= 1)
        v += __shfl_xor_sync(0xFFFFFFFFu, v, o);
    return v;
}

__global__ void __launch_bounds__(256) chamfer_kernel(
    const float* __restrict__ prob,
    const float* __restrict__ gt,
    float* __restrict__ out)
{
    __shared__ __align__(16) float2 scand[MM];  // candidate gt coords for tile
    __shared__ int    scnt;
    __shared__ float  swm[8];
    __shared__ int    s_last;

    const int b    = blockIdx.x;
    const int tid  = threadIdx.x;
    const int lane = tid & 31;
    const int wid  = tid >> 5;

    if (b >= T2_BLOCKS) {
        // ============ TERM 1: one 32x32 pixel tile per block ==============
        const int tb  = b - T2_BLOCKS;
        const int tyy = tb >> 4, txx = tb & 15;       // 16x16 tile grid

        // thread owns a 4-row strip at fixed x; prefetch prob NOW (hides L2)
        const int px  = (txx << 5) + lane;
        const int py0 = (tyy << 5) + (wid << 2);
        const float* prow = prob + py0 * WW + px;
        const float p0 = prow[0], p1 = prow[WW], p2 = prow[2 * WW], p3 = prow[3 * WW];

        const float cy = (float)(tyy * 32) + 15.5f;
        const float cx = (float)(txx * 32) + 15.5f;
        const float2* gt2 = (const float2*)gt;

        // pass 1: per-thread squared distances (center -> 2 gt pts), kept in regs
        float2 Ga = gt2[tid];
        float2 Gb = gt2[tid + 256];
        float dya = cy - Ga.x, dxa = cx - Ga.y;
        float dyb = cy - Gb.x, dxb = cx - Gb.y;
        float d2a = fmaf(dya, dya, dxa * dxa);
        float d2b = fmaf(dyb, dyb, dxb * dxb);

        float md = warp_min_pos(fminf(d2a, d2b));
        if (lane == 0) swm[wid] = md;
        if (tid == 0) scnt = 0;
        __syncthreads();
        float mdall = fminf(fminf(fminf(swm[0], swm[1]), fminf(swm[2], swm[3])),
                            fminf(fminf(swm[4], swm[5]), fminf(swm[6], swm[7])));
        // a gt can be nearest for some tile pixel only if its center distance
        // is <= sqrt(mdall) + 2*half_diag  (triangle inequality + fp slack)
        float T  = sqrtf(mdall) + TWO_HD + 1e-2f;
        float T2 = T * T;

        // pass 2: ballot compaction (one shared atomic per warp, no reload)
        {
            const unsigned lmask = (1u << lane) - 1u;
            const bool ha = (d2a <= T2), hb = (d2b <= T2);
            unsigned ba = __ballot_sync(0xFFFFFFFFu, ha);
            unsigned bb = __ballot_sync(0xFFFFFFFFu, hb);
            int na = __popc(ba);
            int base = 0;
            if (lane == 0) base = atomicAdd(&scnt, na + __popc(bb));
            base = __shfl_sync(0xFFFFFFFFu, base, 0);
            if (ha) scand[base + __popc(ba & lmask)] = Ga;
            if (hb) scand[base + na + __popc(bb & lmask)] = Gb;
        }
        __syncthreads();
        const int cnt = scnt;

        // per-pixel nearest: 4 vertical pixels, dx^2 hoisted, float4 loads
        const float fx  = (float)px;
        const float fy0 = (float)py0;
        float m0 = 1e30f, m1 = 1e30f, m2 = 1e30f, m3 = 1e30f;
        const float4* sc4 = (const float4*)scand;
        int k = 0;
        for (; k + 2 <= cnt; k += 2) {
            float4 C = sc4[k >> 1];          // {gy0,gx0,gy1,gx1}
            float dx0 = fx - C.y,  dx20 = dx0 * dx0;
            float u0  = fy0 - C.x;
            float dx1 = fx - C.w,  dx21 = dx1 * dx1;
            float u1  = fy0 - C.z;
            float a1 = u0 + 1.0f, a2 = u0 + 2.0f, a3 = u0 + 3.0f;
            float b1 = u1 + 1.0f, b2 = u1 + 2.0f, b3 = u1 + 3.0f;
            m0 = fminf(fminf(m0, fmaf(u0, u0, dx20)), fmaf(u1, u1, dx21));
            m1 = fminf(fminf(m1, fmaf(a1, a1, dx20)), fmaf(b1, b1, dx21));
            m2 = fminf(fminf(m2, fmaf(a2, a2, dx20)), fmaf(b2, b2, dx21));
            m3 = fminf(fminf(m3, fmaf(a3, a3, dx20)), fmaf(b3, b3, dx21));
        }
        if (k < cnt) {
            float2 G  = scand[k];
            float dx  = fx - G.y, dx2 = dx * dx;
            float u   = fy0 - G.x;
            float a1 = u + 1.0f, a2 = u + 2.0f, a3 = u + 3.0f;
            m0 = fminf(m0, fmaf(u,  u,  dx2));
            m1 = fminf(m1, fmaf(a1, a1, dx2));
            m2 = fminf(m2, fmaf(a2, a2, dx2));
            m3 = fminf(m3, fmaf(a3, a3, dx2));
        }

        float sp  = (p0 + p1) + (p2 + p3);
        float spd = (p0 * sqrtf(m0) + p1 * sqrtf(m1))
                  + (p2 * sqrtf(m2) + p3 * sqrtf(m3));
        sp  = warp_sum(sp);
        spd = warp_sum(spd);
        __syncthreads();                // reuse swm safely
        if (lane == 0) { swm[wid] = sp; scand[wid].x = spd; }
        __syncthreads();
        if (tid == 0) {
            float a = ((swm[0] + swm[1]) + (swm[2] + swm[3]))
                    + ((swm[4] + swm[5]) + (swm[6] + swm[7]));
            float d = ((scand[0].x + scand[1].x) + (scand[2].x + scand[3].x))
                    + ((scand[4].x + scand[5].x) + (scand[6].x + scand[7].x));
            g_bp[tb]  = a;
            g_bpd[tb] = d;
        }
    } else {
        // ================= TERM 2: one gt point per warp ==================
        const int w = b * 8 + wid;              // 0..511
        const float gy = gt[2 * w];
        const float gx = gt[2 * w + 1];
        const int iy = (int)gy;                 // floor (coords >= 0)
        const int ix = (int)gx;

        // expanding-box exact search: pixels outside box radius R have d > R,
        // and value >= d*(1 - 1.4e-9), so stop once R >= min(q_best, MAXD).
        float qb = 1e30f;
        int R = 4;
        for (;;) {
            int y0 = max(iy - R, 0), y1 = min(iy + R, HH - 1);
            int x0 = max(ix - R, 0), x1 = min(ix + R, WW - 1);
            int Wd  = x1 - x0 + 1;
            int tot = Wd * (y1 - y0 + 1);
            float q = 1e30f;
            // flattened scan: all 32 lanes active
            for (int idx = lane; idx < tot; idx += 32) {
                int row = idx / Wd;
                int xx  = x0 + (idx - row * Wd);
                int yy  = y0 + row;
                float p  = prob[yy * WW + xx];
                float dy = (float)yy - gy;
                float dx = (float)xx - gx;
                float d  = sqrtf(fmaf(dx, dx, dy * dy));
                float p2 = p * p;
                float v  = __fdividef(d + EPSF, fmaf(p2, p2, CREG));
                q = fminf(q, v);
            }
            q  = warp_min_pos(q);
            qb = q;   // box rescans include all previously scanned pixels
            float bound = fminf(qb, MAXD);
            if ((float)R >= bound) break;
            if (y0 == 0 && x0 == 0 && y1 == HH - 1 && x1 == WW - 1) break;
            int Rn = (int)bound + 1;
            R = max(Rn, R * 2);   // guaranteed progress; terminates at image
        }
        if (lane == 0) g_q[w] = fminf(qb, MAXD);
    }

    // ============ completion detection + final reduce by last block =======
    __threadfence();
    __syncthreads();
    if (tid == 0) {
        unsigned int prev = atomicAdd(&g_done, 1u);
        s_last = (prev == GRID_TOT - 1) ? 1 : 0;
    }
    __syncthreads();
    if (s_last) {
        // 3 warps reduce the 3 arrays in parallel (fixed order: deterministic)
        float r = 0.0f;
        if (wid == 0) {
#pragma unroll
            for (int i = 0; i < 8; ++i) r += g_bp[lane * 8 + i];
        } else if (wid == 1) {
#pragma unroll
            for (int i = 0; i < 8; ++i) r += g_bpd[lane * 8 + i];
        } else if (wid == 2) {
#pragma unroll
            for (int i = 0; i < 16; ++i) r += g_q[lane * 16 + i];
        }
        r = warp_sum(r);
        if (lane == 0 && wid < 3) swm[wid] = r;
        __syncthreads();
        if (tid == 0) {
            float term1 = swm[1] / (swm[0] + EPSF);
            float term2 = swm[2] * (1.0f / (float)MM);
            out[0] = term1 + term2;
            g_done = 0;              // reset for next graph replay
            __threadfence();
        }
    }
}

extern "C" void kernel_launch(void* const* d_in, const int* in_sizes, int n_in,
                              void* d_out, int out_size) {
    // prob_map: 262144 elems, gt: 1024 elems, all_img_locations: implicit
    const float* prob = nullptr;
    const float* gt   = nullptr;
    for (int i = 0; i < n_in; ++i) {
        if (in_sizes[i] == HH * WW)      prob = (const float*)d_in[i];
        else if (in_sizes[i] == 2 * MM)  gt   = (const float*)d_in[i];
    }
    chamfer_kernel<<<GRID_TOT, 256>>>(prob, gt, (float*)d_out);
}